// round 1
// baseline (speedup 1.0000x reference)
#include <cuda_runtime.h>
#include <stdint.h>

// Problem constants (fixed by the dataset: v is [32, 2, 512, 512] fp32)
#define NB 32
#define HH 512
#define WW 512
#define HW (HH * WW)          // 262144 = 2^18
#define TOTAL (NB * HW)       // 8388608
#define NO_STEPS 16
#define SCALE 0x1p-16f        // 1 / 2^16

// Ping-pong scratch: warp field stored interleaved as [n][y][x] -> float2(ch0, ch1).
// 64 MiB each (allowed: __device__ globals, no runtime allocation).
__device__ float2 g_bufA[TOTAL];
__device__ float2 g_bufB[TOTAL];

// ---------------------------------------------------------------------------
// Bilinear sample with border clamp, align_corners=False (torch/jax semantics),
// over an interleaved float2 plane (one batch image).
// ---------------------------------------------------------------------------
__device__ __forceinline__ float2 bilerp_f2(const float2* __restrict__ plane,
                                            float gx, float gy) {
    float ix = fminf(fmaxf(((gx + 1.0f) * (float)WW - 1.0f) * 0.5f, 0.0f), (float)(WW - 1));
    float iy = fminf(fmaxf(((gy + 1.0f) * (float)HH - 1.0f) * 0.5f, 0.0f), (float)(HH - 1));
    float fx0 = floorf(ix);
    float fy0 = floorf(iy);
    int x0 = (int)fx0;
    int y0 = (int)fy0;
    int x1 = min(x0 + 1, WW - 1);
    int y1 = min(y0 + 1, HH - 1);
    float wx = ix - fx0;
    float wy = iy - fy0;
    float2 a = plane[y0 * WW + x0];
    float2 b = plane[y0 * WW + x1];
    float2 c = plane[y1 * WW + x0];
    float2 d = plane[y1 * WW + x1];
    float owx = 1.0f - wx;
    float owy = 1.0f - wy;
    float2 top, bot, r;
    top.x = a.x * owx + b.x * wx;
    top.y = a.y * owx + b.y * wx;
    bot.x = c.x * owx + d.x * wx;
    bot.y = c.y * owx + d.y * wx;
    r.x = top.x * owy + bot.x * wy;
    r.y = top.y * owy + bot.y * wy;
    return r;
}

// Same, but sampling directly from the NCHW v tensor with the 2^-16 scale
// applied to each tap (used by the fused first step).
__device__ __forceinline__ float2 bilerp_v(const float* __restrict__ p0,
                                           const float* __restrict__ p1,
                                           float gx, float gy) {
    float ix = fminf(fmaxf(((gx + 1.0f) * (float)WW - 1.0f) * 0.5f, 0.0f), (float)(WW - 1));
    float iy = fminf(fmaxf(((gy + 1.0f) * (float)HH - 1.0f) * 0.5f, 0.0f), (float)(HH - 1));
    float fx0 = floorf(ix);
    float fy0 = floorf(iy);
    int x0 = (int)fx0;
    int y0 = (int)fy0;
    int x1 = min(x0 + 1, WW - 1);
    int y1 = min(y0 + 1, HH - 1);
    float wx = ix - fx0;
    float wy = iy - fy0;
    int i00 = y0 * WW + x0, i01 = y0 * WW + x1, i10 = y1 * WW + x0, i11 = y1 * WW + x1;
    float owx = 1.0f - wx;
    float owy = 1.0f - wy;
    float2 r;
    {
        float a = p0[i00] * SCALE, b = p0[i01] * SCALE, c = p0[i10] * SCALE, d = p0[i11] * SCALE;
        float top = a * owx + b * wx;
        float bot = c * owx + d * wx;
        r.x = top * owy + bot * wy;
    }
    {
        float a = p1[i00] * SCALE, b = p1[i01] * SCALE, c = p1[i10] * SCALE, d = p1[i11] * SCALE;
        float top = a * owx + b * wx;
        float bot = c * owx + d * wx;
        r.y = top * owy + bot * wy;
    }
    return r;
}

// ---------------------------------------------------------------------------
// Step 1 (fused init): wf0 = v * 2^-16 ; wf1 = wf0 + sample(wf0, id + wf0)
// reads v (NCHW), writes g_bufB (interleaved)
// ---------------------------------------------------------------------------
__global__ __launch_bounds__(256)
void svf_step_first(const float* __restrict__ v,
                    const float2* __restrict__ ig,
                    float2* __restrict__ dst) {
    int i = blockIdx.x * blockDim.x + threadIdx.x;
    if (i >= TOTAL) return;
    int yx = i & (HW - 1);
    int n  = i >> 18;
    const float* p0 = v + (size_t)n * 2 * HW;        // channel 0 plane
    const float* p1 = p0 + HW;                       // channel 1 plane
    float2 s;
    s.x = p0[yx] * SCALE;
    s.y = p1[yx] * SCALE;
    float2 g = ig[yx];
    float2 sm = bilerp_v(p0, p1, g.x + s.x, g.y + s.y);
    float2 o;
    o.x = s.x + sm.x;
    o.y = s.y + sm.y;
    dst[i] = o;
}

// ---------------------------------------------------------------------------
// Generic middle step: wf1 = wf0 + sample(wf0, id + wf0)
// ---------------------------------------------------------------------------
__global__ __launch_bounds__(256)
void svf_step(const float2* __restrict__ src,
              const float2* __restrict__ ig,
              float2* __restrict__ dst) {
    int i = blockIdx.x * blockDim.x + threadIdx.x;
    if (i >= TOTAL) return;
    int yx = i & (HW - 1);
    int n  = i >> 18;
    float2 s = src[i];
    float2 g = ig[yx];
    const float2* plane = src + ((size_t)n << 18);
    float2 sm = bilerp_f2(plane, g.x + s.x, g.y + s.y);
    float2 o;
    o.x = s.x + sm.x;
    o.y = s.y + sm.y;
    dst[i] = o;
}

// ---------------------------------------------------------------------------
// Last step (fused epilogue): computes wf_final and writes BOTH outputs to
// d_out in NCHW: [transformation (N,2,H,W) | warp_field (N,2,H,W)]
// ---------------------------------------------------------------------------
__global__ __launch_bounds__(256)
void svf_step_last(const float2* __restrict__ src,
                   const float2* __restrict__ ig,
                   float* __restrict__ out) {
    int i = blockIdx.x * blockDim.x + threadIdx.x;
    if (i >= TOTAL) return;
    int yx = i & (HW - 1);
    int n  = i >> 18;
    float2 s = src[i];
    float2 g = ig[yx];
    const float2* plane = src + ((size_t)n << 18);
    float2 sm = bilerp_f2(plane, g.x + s.x, g.y + s.y);
    float wf0 = s.x + sm.x;
    float wf1 = s.y + sm.y;
    size_t base = ((size_t)n * 2) * HW + yx;     // channel-0 plane offset (NCHW)
    const size_t half = (size_t)NB * 2 * HW;     // start of warp_field output
    out[base]            = wf0 + g.x;            // transformation ch0
    out[base + HW]       = wf1 + g.y;            // transformation ch1
    out[half + base]     = wf0;                  // warp_field ch0
    out[half + base + HW] = wf1;                 // warp_field ch1
}

extern "C" void kernel_launch(void* const* d_in, const int* in_sizes, int n_in,
                              void* d_out, int out_size) {
    const float*  v  = (const float*)d_in[0];
    const float2* ig = (const float2*)d_in[1];   // [1,H,W,2] contiguous -> float2
    float* out = (float*)d_out;

    float2* bufA = nullptr;
    float2* bufB = nullptr;
    cudaGetSymbolAddress((void**)&bufA, g_bufA);
    cudaGetSymbolAddress((void**)&bufB, g_bufB);

    const int threads = 256;
    const int blocks = (TOTAL + threads - 1) / threads;

    // step 1: v -> bufA
    svf_step_first<<<blocks, threads>>>(v, ig, bufA);

    // steps 2..15: ping-pong A<->B  (after step k, result in: k odd -> A, even -> B)
    float2* cur = bufA;
    float2* nxt = bufB;
    for (int k = 2; k <= NO_STEPS - 1; ++k) {
        svf_step<<<blocks, threads>>>(cur, ig, nxt);
        float2* t = cur; cur = nxt; nxt = t;
    }

    // step 16: cur -> d_out (transformation + warp_field, NCHW)
    svf_step_last<<<blocks, threads>>>(cur, ig, out);
}

// round 4
// speedup vs baseline: 1.0861x; 1.0861x over previous
#include <cuda_runtime.h>
#include <stdint.h>

// Problem constants (fixed: v is [32, 2, 512, 512] fp32)
#define NB 32
#define HH 512
#define WW 512
#define HW (HH * WW)          // 262144 = 2^18
#define TOTAL (NB * HW)       // 8388608
#define NO_STEPS 16
#define SCALE 0x1p-16f        // 1 / 2^16

// Batch grouping for L2 residency: 16 images -> 2x32MiB ping-pong working set.
#define G_IMGS 16
#define N_GROUPS (NB / G_IMGS)
#define G_PIX (G_IMGS * HW)

// Ping-pong scratch: warp field interleaved [n][y][x] -> float2(ch0, ch1).
__device__ float2 g_bufA[TOTAL];
__device__ float2 g_bufB[TOTAL];

// ---------------------------------------------------------------------------
// Bilinear sample, border clamp, align_corners=False, interleaved float2 plane.
// ---------------------------------------------------------------------------
__device__ __forceinline__ float2 sample_plane(const float2* __restrict__ plane,
                                               float sx, float sy) {
    float ix = fminf(fmaxf(((sx + 1.0f) * (float)WW - 1.0f) * 0.5f, 0.0f), (float)(WW - 1));
    float iy = fminf(fmaxf(((sy + 1.0f) * (float)HH - 1.0f) * 0.5f, 0.0f), (float)(HH - 1));
    float fx0 = floorf(ix);
    float fy0 = floorf(iy);
    int x0 = (int)fx0, y0 = (int)fy0;
    int x1 = min(x0 + 1, WW - 1);
    int y1 = min(y0 + 1, HH - 1);
    float wx = ix - fx0, wy = iy - fy0;
    float2 a = __ldg(plane + y0 * WW + x0);
    float2 b = __ldg(plane + y0 * WW + x1);
    float2 c = __ldg(plane + y1 * WW + x0);
    float2 d = __ldg(plane + y1 * WW + x1);
    float owx = 1.0f - wx, owy = 1.0f - wy;
    float2 top, bot, r;
    top.x = a.x * owx + b.x * wx;  top.y = a.y * owx + b.y * wx;
    bot.x = c.x * owx + d.x * wx;  bot.y = c.y * owx + d.y * wx;
    r.x = top.x * owy + bot.x * wy;
    r.y = top.y * owy + bot.y * wy;
    return r;
}

// Bilinear over NCHW v planes with 2^-16 scale folded into every tap.
__device__ __forceinline__ float2 sample_v(const float* __restrict__ p0,
                                           const float* __restrict__ p1,
                                           float sx, float sy) {
    float ix = fminf(fmaxf(((sx + 1.0f) * (float)WW - 1.0f) * 0.5f, 0.0f), (float)(WW - 1));
    float iy = fminf(fmaxf(((sy + 1.0f) * (float)HH - 1.0f) * 0.5f, 0.0f), (float)(HH - 1));
    float fx0 = floorf(ix);
    float fy0 = floorf(iy);
    int x0 = (int)fx0, y0 = (int)fy0;
    int x1 = min(x0 + 1, WW - 1);
    int y1 = min(y0 + 1, HH - 1);
    float wx = ix - fx0, wy = iy - fy0;
    int i00 = y0 * WW + x0, i01 = y0 * WW + x1, i10 = y1 * WW + x0, i11 = y1 * WW + x1;
    float owx = 1.0f - wx, owy = 1.0f - wy;
    float2 r;
    {
        float a = __ldg(p0 + i00) * SCALE, b = __ldg(p0 + i01) * SCALE;
        float c = __ldg(p0 + i10) * SCALE, d = __ldg(p0 + i11) * SCALE;
        r.x = (a * owx + b * wx) * owy + (c * owx + d * wx) * wy;
    }
    {
        float a = __ldg(p1 + i00) * SCALE, b = __ldg(p1 + i01) * SCALE;
        float c = __ldg(p1 + i10) * SCALE, d = __ldg(p1 + i11) * SCALE;
        r.y = (a * owx + b * wx) * owy + (c * owx + d * wx) * wy;
    }
    return r;
}

// ---------------------------------------------------------------------------
// Step 1 fused with init: wf0 = v*2^-16 ; out = wf0 + sample(wf0, id+wf0)
// Processes one group of G_IMGS images; 2 pixels per thread.
// ig: identity grid loaded from input (exact linspace values), [H*W] float2.
// ---------------------------------------------------------------------------
__global__ __launch_bounds__(256)
void svf_first_g(const float* __restrict__ v, const float2* __restrict__ ig,
                 float2* __restrict__ dst, int n0) {
    int t = blockIdx.x * blockDim.x + threadIdx.x;   // G_PIX/2 threads
    int p = t << 1;                                  // pixel pair start
    if (p >= G_PIX) return;
    int local = p & (HW - 1);
    int img = n0 + (p >> 18);
    const float* p0 = v + (size_t)img * 2 * HW;
    const float* p1 = p0 + HW;
    // center values for two adjacent pixels (same row; 512 is even)
    float2 c0 = *reinterpret_cast<const float2*>(p0 + local);
    float2 c1 = *reinterpret_cast<const float2*>(p1 + local);
    float wfx0 = c0.x * SCALE, wfx1 = c0.y * SCALE;
    float wfy0 = c1.x * SCALE, wfy1 = c1.y * SCALE;
    // grid for both pixels: (gx0, gy0, gx1, gy1)
    float4 g = __ldg(reinterpret_cast<const float4*>(ig + local));
    float2 sm0 = sample_v(p0, p1, g.x + wfx0, g.y + wfy0);
    float2 sm1 = sample_v(p0, p1, g.z + wfx1, g.w + wfy1);
    float4 o;
    o.x = wfx0 + sm0.x;  o.y = wfy0 + sm0.y;
    o.z = wfx1 + sm1.x;  o.w = wfy1 + sm1.y;
    *reinterpret_cast<float4*>(dst + ((size_t)img << 18) + local) = o;
}

// ---------------------------------------------------------------------------
// Middle step: wf' = wf + sample(wf, id + wf), one group, 2 px/thread.
// ---------------------------------------------------------------------------
__global__ __launch_bounds__(256)
void svf_step_g(const float2* __restrict__ src, const float2* __restrict__ ig,
                float2* __restrict__ dst, int n0) {
    int t = blockIdx.x * blockDim.x + threadIdx.x;
    int p = t << 1;
    if (p >= G_PIX) return;
    int local = p & (HW - 1);
    int img = n0 + (p >> 18);
    const float2* plane = src + ((size_t)img << 18);
    float4 s = *reinterpret_cast<const float4*>(plane + local);
    float4 g = __ldg(reinterpret_cast<const float4*>(ig + local));
    float2 sm0 = sample_plane(plane, g.x + s.x, g.y + s.y);
    float2 sm1 = sample_plane(plane, g.z + s.z, g.w + s.w);
    float4 o;
    o.x = s.x + sm0.x;  o.y = s.y + sm0.y;
    o.z = s.z + sm1.x;  o.w = s.w + sm1.y;
    *reinterpret_cast<float4*>(dst + ((size_t)img << 18) + local) = o;
}

// ---------------------------------------------------------------------------
// Last step fused with epilogue: writes transformation & warp_field (NCHW).
// d_out layout: [transformation (N,2,H,W) | warp_field (N,2,H,W)]
// ---------------------------------------------------------------------------
__global__ __launch_bounds__(256)
void svf_last_g(const float2* __restrict__ src, const float2* __restrict__ ig,
                float* __restrict__ out, int n0) {
    int t = blockIdx.x * blockDim.x + threadIdx.x;
    int p = t << 1;
    if (p >= G_PIX) return;
    int local = p & (HW - 1);
    int img = n0 + (p >> 18);
    const float2* plane = src + ((size_t)img << 18);
    float4 s = *reinterpret_cast<const float4*>(plane + local);
    float4 g = __ldg(reinterpret_cast<const float4*>(ig + local));
    float2 sm0 = sample_plane(plane, g.x + s.x, g.y + s.y);
    float2 sm1 = sample_plane(plane, g.z + s.z, g.w + s.w);
    float wfx0 = s.x + sm0.x, wfy0 = s.y + sm0.y;
    float wfx1 = s.z + sm1.x, wfy1 = s.w + sm1.y;
    size_t base = ((size_t)img * 2) * HW + local;   // ch0 plane offset (NCHW)
    const size_t half = (size_t)NB * 2 * HW;        // start of warp_field output
    float2 tx;  tx.x = wfx0 + g.x;  tx.y = wfx1 + g.z;
    float2 ty;  ty.x = wfy0 + g.y;  ty.y = wfy1 + g.w;
    float2 wxo; wxo.x = wfx0;       wxo.y = wfx1;
    float2 wyo; wyo.x = wfy0;       wyo.y = wfy1;
    *reinterpret_cast<float2*>(out + base)              = tx;  // transformation ch0
    *reinterpret_cast<float2*>(out + base + HW)         = ty;  // transformation ch1
    *reinterpret_cast<float2*>(out + half + base)       = wxo; // warp_field ch0
    *reinterpret_cast<float2*>(out + half + base + HW)  = wyo; // warp_field ch1
}

extern "C" void kernel_launch(void* const* d_in, const int* in_sizes, int n_in,
                              void* d_out, int out_size) {
    const float*  v  = (const float*)d_in[0];
    const float2* ig = (const float2*)d_in[1];   // [1,H,W,2] contiguous -> float2 per px
    float* out = (float*)d_out;

    float2* bufA = nullptr;
    float2* bufB = nullptr;
    cudaGetSymbolAddress((void**)&bufA, g_bufA);
    cudaGetSymbolAddress((void**)&bufB, g_bufB);

    const int threads = 256;
    const int blocks = (G_PIX / 2 + threads - 1) / threads;   // 2 px per thread

    for (int g = 0; g < N_GROUPS; ++g) {
        int n0 = g * G_IMGS;
        // step 1: v -> bufA (group-local region)
        svf_first_g<<<blocks, threads>>>(v, ig, bufA, n0);
        // steps 2..15: ping-pong within the group's region (stays in L2)
        float2* cur = bufA;
        float2* nxt = bufB;
        for (int k = 2; k <= NO_STEPS - 1; ++k) {
            svf_step_g<<<blocks, threads>>>(cur, ig, nxt, n0);
            float2* tswap = cur; cur = nxt; nxt = tswap;
        }
        // step 16: cur -> d_out
        svf_last_g<<<blocks, threads>>>(cur, ig, out, n0);
    }
}